// round 9
// baseline (speedup 1.0000x reference)
#include <cuda_runtime.h>
#include <cstdint>

// ---------------------------------------------------------------------------
// Problem constants
// ---------------------------------------------------------------------------
#define BATCH 4
// Level A: coarse = xyz2 (512 pts/b), queries = xyz1 (2048 pts/b)
#define SA 512
#define NA 2048
#define GA 16
#define CA (GA*GA*GA)
// Level B: coarse = xyz1 (2048 pts/b), queries = xyz0 (8192 pts/b)
#define SB 2048
#define NB 8192
#define GB 32
#define CB (GB*GB*GB)          // 32768
#define BOUND 4.5f
#define HA (2.0f*BOUND/GA)     // 0.5625
#define HB (2.0f*BOUND/GB)     // 0.28125

#define D_IP1 512
#define DOUT 896
#define NOUT 8192

// ---------------------------------------------------------------------------
// Device scratch (static: no runtime allocation allowed)
// ---------------------------------------------------------------------------
__device__ int            g_cntA[BATCH*CA];
__device__ int            g_cntB[BATCH*CB];
__device__ int            g_qcntA[BATCH*CA];
__device__ int            g_qcntB[BATCH*CB];
__device__ int            g_cellA[BATCH*SA];
__device__ int            g_cellB[BATCH*SB];
__device__ int            g_qcellA[BATCH*NA];
__device__ int            g_qcellB[BATCH*NB];
__device__ float4         g_ptsA[BATCH*SA];   // (x,y,z,Sb)
__device__ float4         g_ptsB[BATCH*SB];
__device__ unsigned short g_permA[BATCH*SA];  // sorted pos -> original idx
__device__ unsigned short g_permB[BATCH*SB];
__device__ float4         g_qA[BATCH*NA];     // sorted queries (x,y,z,orig)
__device__ float4         g_qB[BATCH*NB];
__device__ float4         g_iwA[BATCH*NA];    // {i0|i1<<16, i2, w0, w1}
__device__ float4         g_iwB[BATCH*NB];
__device__ float          g_ip1[(size_t)BATCH*D_IP1*NA];

// ---------------------------------------------------------------------------
// Helpers
// ---------------------------------------------------------------------------
__device__ __forceinline__ int cell1d(float x, float invh, int G) {
    int c = (int)floorf((x + BOUND) * invh);
    return min(max(c, 0), G - 1);
}

__device__ __forceinline__ unsigned ford(float f) {
    int ib = __float_as_int(f);
    return (unsigned)ib ^ (unsigned)((ib >> 31) | 0x80000000);
}
__device__ __forceinline__ float funord(unsigned o) {
    int ib = (o & 0x80000000u) ? (int)(o ^ 0x80000000u) : (int)~o;
    return __int_as_float(ib);
}

// ---------------------------------------------------------------------------
// Fused grid build
// ---------------------------------------------------------------------------
#define OFF1 (BATCH*SA)                    // 2048
#define OFF2 (OFF1 + BATCH*SB)             // 10240
#define OFF3 (OFF2 + BATCH*NA)             // 18432
#define TOTPTS (OFF3 + BATCH*NB)           // 51200

__global__ void k_zero4(int* __restrict__ a0, int* __restrict__ a1,
                        int* __restrict__ a2, int* __restrict__ a3) {
    int i = blockIdx.x * blockDim.x + threadIdx.x;
    if (i < BATCH*CA) { a0[i] = 0; a2[i] = 0; }
    if (i < BATCH*CB) { a1[i] = 0; a3[i] = 0; }
}

__global__ void k_bin4(const float* __restrict__ xyz0,
                       const float* __restrict__ xyz1,
                       const float* __restrict__ xyz2,
                       int* __restrict__ cntA,  int* __restrict__ cellA,
                       int* __restrict__ cntB,  int* __restrict__ cellB,
                       int* __restrict__ qcntA, int* __restrict__ qcellA,
                       int* __restrict__ qcntB, int* __restrict__ qcellB) {
    int gi = blockIdx.x * blockDim.x + threadIdx.x;
    if (gi >= TOTPTS) return;
    const float* xyz; int S, G; float invh; int *cnt, *cell; int i;
    if (gi < OFF1)      { i = gi;        xyz = xyz2; S = SA; G = GA; invh = 1.0f/HA; cnt = cntA;  cell = cellA;  }
    else if (gi < OFF2) { i = gi - OFF1; xyz = xyz1; S = SB; G = GB; invh = 1.0f/HB; cnt = cntB;  cell = cellB;  }
    else if (gi < OFF3) { i = gi - OFF2; xyz = xyz1; S = NA; G = GA; invh = 1.0f/HA; cnt = qcntA; cell = qcellA; }
    else                { i = gi - OFF3; xyz = xyz0; S = NB; G = GB; invh = 1.0f/HB; cnt = qcntB; cell = qcellB; }
    int b = i / S;
    const float* p = xyz + 3 * i;
    int cx = cell1d(p[0], invh, G);
    int cy = cell1d(p[1], invh, G);
    int cz = cell1d(p[2], invh, G);
    int c = (cz * G + cy) * G + cx;
    cell[i] = c;
    atomicAdd(&cnt[b * G * G * G + c], 1);
}

// Exclusive prefix sum; 16 blocks: [which*4 + b]
__global__ void k_scan4(int* __restrict__ cntA, int* __restrict__ cntB,
                        int* __restrict__ qcntA, int* __restrict__ qcntB) {
    __shared__ int ssum[1024];
    int which = blockIdx.x >> 2;
    int b = blockIdx.x & 3;
    int* base; int ncells;
    if (which == 0)      { base = cntA;  ncells = CA; }
    else if (which == 1) { base = cntB;  ncells = CB; }
    else if (which == 2) { base = qcntA; ncells = CA; }
    else                 { base = qcntB; ncells = CB; }
    int* a = base + b * ncells;
    int t = threadIdx.x;
    int chunk = (ncells + 1023) >> 10;
    int lo = t * chunk;
    int hi = min(lo + chunk, ncells);
    int s = 0;
    for (int i = lo; i < hi; ++i) s += a[i];
    ssum[t] = s;
    __syncthreads();
    for (int off = 1; off < 1024; off <<= 1) {
        int v = (t >= off) ? ssum[t - off] : 0;
        __syncthreads();
        ssum[t] += v;
        __syncthreads();
    }
    int run = (t == 0) ? 0 : ssum[t - 1];
    for (int i = lo; i < hi; ++i) { int c = a[i]; a[i] = run; run += c; }
}

__global__ void k_scatter4(const float* __restrict__ xyz0,
                           const float* __restrict__ xyz1,
                           const float* __restrict__ xyz2,
                           int* __restrict__ cntA,  const int* __restrict__ cellA,
                           int* __restrict__ cntB,  const int* __restrict__ cellB,
                           int* __restrict__ qcntA, const int* __restrict__ qcellA,
                           int* __restrict__ qcntB, const int* __restrict__ qcellB,
                           float4* __restrict__ ptsA, unsigned short* __restrict__ permA,
                           float4* __restrict__ ptsB, unsigned short* __restrict__ permB,
                           float4* __restrict__ qA, float4* __restrict__ qB) {
    int gi = blockIdx.x * blockDim.x + threadIdx.x;
    if (gi >= TOTPTS) return;
    if (gi < OFF2) {
        const float* xyz; int S, ncells; int* cnt; const int* cell;
        float4* pts; unsigned short* perm; int i;
        if (gi < OFF1) { i = gi;        xyz = xyz2; S = SA; ncells = CA; cnt = cntA; cell = cellA; pts = ptsA; perm = permA; }
        else           { i = gi - OFF1; xyz = xyz1; S = SB; ncells = CB; cnt = cntB; cell = cellB; pts = ptsB; perm = permB; }
        int b = i / S;
        int s = i - b * S;
        int pos = atomicAdd(&cnt[b * ncells + cell[i]], 1);
        const float* p = xyz + 3 * i;
        float x = p[0], y = p[1], z = p[2];
        float Sb = __fadd_rn(__fadd_rn(__fmul_rn(x, x), __fmul_rn(y, y)), __fmul_rn(z, z));
        pts[b * S + pos] = make_float4(x, y, z, Sb);
        perm[b * S + pos] = (unsigned short)s;
    } else {
        const float* xyz; int S, ncells; int* cnt; const int* cell; float4* q; int i;
        if (gi < OFF3) { i = gi - OFF2; xyz = xyz1; S = NA; ncells = CA; cnt = qcntA; cell = qcellA; q = qA; }
        else           { i = gi - OFF3; xyz = xyz0; S = NB; ncells = CB; cnt = qcntB; cell = qcellB; q = qB; }
        int b = i / S;
        int s = i - b * S;
        int pos = atomicAdd(&cnt[b * ncells + cell[i]], 1);
        const float* p = xyz + 3 * i;
        q[b * S + pos] = make_float4(p[0], p[1], p[2], __int_as_float(s));
    }
}

// ---------------------------------------------------------------------------
// 3-NN query. Distances computed EXACTLY like the reference:
//   d = (Sa + Sb) - 2*dot,  dot = fma(a2,b2, fma(a1,b1, RN(a0*b0)))
// ---------------------------------------------------------------------------
__device__ __forceinline__ void scan_range(
    const float4* __restrict__ pp, int s0, int s1,
    float px, float py, float pz, float Sa,
    unsigned long long& k1, unsigned long long& k2, unsigned long long& k3)
{
    for (int i = s0; i < s1; ++i) {
        float4 Q = __ldg(pp + i);
        float dot = __fmaf_rn(pz, Q.z, __fmaf_rn(py, Q.y, __fmul_rn(px, Q.x)));
        float d = __fsub_rn(__fadd_rn(Sa, Q.w), __fmul_rn(2.0f, dot));
        unsigned long long key = ((unsigned long long)ford(d) << 32) | (unsigned)i;
        if (key < k3) {
            unsigned long long t = min(k2, key);
            k3 = max(k2, key);
            k2 = t;
            t = min(k1, k2);
            k2 = max(k1, k2);
            k1 = t;
        }
    }
}

__device__ __forceinline__ void run_query(
    const float4* __restrict__ qs, int N,
    const int* __restrict__ cnt, const float4* __restrict__ pts,
    const unsigned short* __restrict__ perm, int S,
    int G, float h, float invh,
    float4* __restrict__ iw, int gid)
{
    float4 q4 = qs[gid];
    int b = gid / N;
    float px = q4.x, py = q4.y, pz = q4.z;
    int orig = __float_as_int(q4.w);
    float Sa = __fadd_rn(__fadd_rn(__fmul_rn(px, px), __fmul_rn(py, py)),
                         __fmul_rn(pz, pz));
    int cx = cell1d(px, invh, G);
    int cy = cell1d(py, invh, G);
    int cz = cell1d(pz, invh, G);
    const int*    cc = cnt + b * G * G * G;
    const float4* pp = pts + b * S;

    unsigned long long k1 = ~0ull, k2 = ~0ull, k3 = ~0ull;

    for (int r = 0; r < G; ++r) {
        int zlo = max(cz - r, 0), zhi = min(cz + r, G - 1);
        int ylo = max(cy - r, 0), yhi = min(cy + r, G - 1);
        int xlo = max(cx - r, 0), xhi = min(cx + r, G - 1);
        for (int z = zlo; z <= zhi; ++z) {
            bool zface = (z == cz - r) || (z == cz + r);
            for (int y = ylo; y <= yhi; ++y) {
                bool face = zface || (y == cy - r) || (y == cy + r);
                int rowbase = (z * G + y) * G;
                if (face) {
                    int c0 = rowbase + xlo, c1 = rowbase + xhi;
                    int s0 = (c0 == 0) ? 0 : cc[c0 - 1];
                    int s1 = cc[c1];
                    scan_range(pp, s0, s1, px, py, pz, Sa, k1, k2, k3);
                } else {
                    int xa = cx - r, xb_ = cx + r;
                    if (xa >= 0) {
                        int c = rowbase + xa;
                        int s0 = (c == 0) ? 0 : cc[c - 1];
                        scan_range(pp, s0, cc[c], px, py, pz, Sa, k1, k2, k3);
                    }
                    if (xb_ < G) {
                        int c = rowbase + xb_;
                        scan_range(pp, cc[c - 1], cc[c], px, py, pz, Sa, k1, k2, k3);
                    }
                }
            }
        }
        if (k3 != ~0ull) {
            float rb = r * h;
            unsigned thr = ford(rb * rb - 1e-5f);
            if ((unsigned)(k3 >> 32) <= thr) break;
        }
    }

    float d0 = funord((unsigned)(k1 >> 32));
    float d1 = funord((unsigned)(k2 >> 32));
    float d2 = funord((unsigned)(k3 >> 32));
    float r0 = __frcp_rn(__fadd_rn(d0, 1e-8f));
    float r1 = __frcp_rn(__fadd_rn(d1, 1e-8f));
    float r2 = __frcp_rn(__fadd_rn(d2, 1e-8f));
    float s  = __fadd_rn(__fadd_rn(r0, r1), r2);
    float w0 = __fdiv_rn(r0, s);
    float w1 = __fdiv_rn(r1, s);

    const unsigned short* pm = perm + b * S;
    int i0 = pm[(unsigned)(k1 & 0xFFFFFFFFu)];
    int i1 = pm[(unsigned)(k2 & 0xFFFFFFFFu)];
    int i2 = pm[(unsigned)(k3 & 0xFFFFFFFFu)];

    float4 o;
    o.x = __int_as_float(i0 | (i1 << 16));
    o.y = __int_as_float(i2);
    o.z = w0;
    o.w = w1;   // w2 = 1 - w0 - w1
    iw[b * N + orig] = o;
}

#define QBLK 64
#define NBLKA ((BATCH*NA)/QBLK)   // 128
#define NBLKB ((BATCH*NB)/QBLK)   // 512

__global__ void k_query_all(
    const float4* __restrict__ qA, const int* __restrict__ cntA,
    const float4* __restrict__ ptsA, const unsigned short* __restrict__ permA,
    float4* __restrict__ iwA,
    const float4* __restrict__ qB, const int* __restrict__ cntB,
    const float4* __restrict__ ptsB, const unsigned short* __restrict__ permB,
    float4* __restrict__ iwB)
{
    if (blockIdx.x < NBLKA) {
        int gid = blockIdx.x * QBLK + threadIdx.x;
        run_query(qA, NA, cntA, ptsA, permA, SA, GA, HA, 1.0f / HA, iwA, gid);
    } else {
        int gid = (blockIdx.x - NBLKA) * QBLK + threadIdx.x;
        run_query(qB, NB, cntB, ptsB, permB, SB, GB, HB, 1.0f / HB, iwB, gid);
    }
}

// ---------------------------------------------------------------------------
// Stage-1 interpolation (TRANSPOSED smem: sm[s*DT + d] -> float4 LDS reads)
// ip1[b][d][n] = sum_k w_k * x2[b][d][idx_k]
// ---------------------------------------------------------------------------
template <int DT>   // DT multiple of 4
__global__ void k_gather(const float* __restrict__ feat, int D, int S, int N,
                         const float4* __restrict__ iw, float* __restrict__ out) {
    extern __shared__ float sm[];
    int b = blockIdx.y;
    int d0 = blockIdx.x * DT;

    // fill transposed: sm[s*DT + j] = feat[b][d0+j][s]
    {
        const int s4cnt = S / 4;
        for (int i = threadIdx.x; i < DT * s4cnt; i += blockDim.x) {
            int j = i / s4cnt;
            int s4 = (i - j * s4cnt) * 4;
            const float4 v = ((const float4*)(feat + ((size_t)b * D + d0 + j) * S))[s4 >> 2];
            sm[(s4 + 0) * DT + j] = v.x;
            sm[(s4 + 1) * DT + j] = v.y;
            sm[(s4 + 2) * DT + j] = v.z;
            sm[(s4 + 3) * DT + j] = v.w;
        }
    }
    __syncthreads();

    const float4* iwb = iw + b * N;
    float* ob = out + ((size_t)b * D + d0) * N;
    for (int n = threadIdx.x; n < N; n += blockDim.x) {
        float4 v = iwb[n];
        unsigned ii = (unsigned)__float_as_int(v.x);
        int i0 = ii & 0xFFFF, i1 = ii >> 16;
        int i2 = __float_as_int(v.y);
        float w0 = v.z, w1 = v.w, w2 = 1.0f - w0 - w1;
        const float4* p0 = (const float4*)(sm + i0 * DT);
        const float4* p1 = (const float4*)(sm + i1 * DT);
        const float4* p2 = (const float4*)(sm + i2 * DT);
#pragma unroll
        for (int c = 0; c < DT / 4; ++c) {
            float4 a = p0[c], bb = p1[c], cc = p2[c];
            ob[(size_t)(4*c + 0) * N + n] = fmaf(w0, a.x, fmaf(w1, bb.x, w2 * cc.x));
            ob[(size_t)(4*c + 1) * N + n] = fmaf(w0, a.y, fmaf(w1, bb.y, w2 * cc.y));
            ob[(size_t)(4*c + 2) * N + n] = fmaf(w0, a.z, fmaf(w1, bb.z, w2 * cc.z));
            ob[(size_t)(4*c + 3) * N + n] = fmaf(w0, a.w, fmaf(w1, bb.w, w2 * cc.w));
        }
    }
}

// ---------------------------------------------------------------------------
// Final stage-2 interpolation into rows [128,896), x0 copy fused as extra blocks.
// TRANSPOSED smem: sm[s*DT + d].
// ---------------------------------------------------------------------------
#define FBLK_INTERP 96    // (896-128)/8
#define FBLK_COPY 16
template <int DT>
__global__ void k_final(const float* __restrict__ x0,
                        const float* __restrict__ x1, const float* __restrict__ ip1,
                        const float4* __restrict__ iw, float* __restrict__ out) {
    extern __shared__ float sm[];
    const int S = 2048, N = 8192;
    int b = blockIdx.y;

    if (blockIdx.x >= FBLK_INTERP) {
        // pure copy of x0 rows [0,128)
        int cb = blockIdx.x - FBLK_INTERP;
        const int per_b = 128 * 8192 / 4;             // 262144 float4
        const int per_blk = per_b / FBLK_COPY;        // 16384
        const float4* s = (const float4*)(x0 + (size_t)b * 128 * 8192);
        float4*       d = (float4*)(out + (size_t)b * DOUT * 8192);
        int lo = cb * per_blk;
        for (int i = lo + threadIdx.x; i < lo + per_blk; i += blockDim.x)
            d[i] = s[i];
        return;
    }

    int d0 = 128 + blockIdx.x * DT;

    // fill transposed
    {
        const int s4cnt = S / 4;  // 512
        for (int i = threadIdx.x; i < DT * s4cnt; i += blockDim.x) {
            int j = i / s4cnt;
            int s4 = (i - j * s4cnt) * 4;
            int d = d0 + j;
            const float* src = (d < 384)
                ? (x1  + ((size_t)b * 256 + (d - 128)) * S)
                : (ip1 + ((size_t)b * 512 + (d - 384)) * S);
            const float4 v = ((const float4*)src)[s4 >> 2];
            sm[(s4 + 0) * DT + j] = v.x;
            sm[(s4 + 1) * DT + j] = v.y;
            sm[(s4 + 2) * DT + j] = v.z;
            sm[(s4 + 3) * DT + j] = v.w;
        }
    }
    __syncthreads();

    const float4* iwb = iw + b * N;
    float* ob = out + ((size_t)b * DOUT + d0) * N;
    for (int n = threadIdx.x; n < N; n += blockDim.x) {
        float4 v = iwb[n];
        unsigned ii = (unsigned)__float_as_int(v.x);
        int i0 = ii & 0xFFFF, i1 = ii >> 16;
        int i2 = __float_as_int(v.y);
        float w0 = v.z, w1 = v.w, w2 = 1.0f - w0 - w1;
        const float4* p0 = (const float4*)(sm + i0 * DT);
        const float4* p1 = (const float4*)(sm + i1 * DT);
        const float4* p2 = (const float4*)(sm + i2 * DT);
#pragma unroll
        for (int c = 0; c < DT / 4; ++c) {
            float4 a = p0[c], bb = p1[c], cc = p2[c];
            ob[(size_t)(4*c + 0) * N + n] = fmaf(w0, a.x, fmaf(w1, bb.x, w2 * cc.x));
            ob[(size_t)(4*c + 1) * N + n] = fmaf(w0, a.y, fmaf(w1, bb.y, w2 * cc.y));
            ob[(size_t)(4*c + 2) * N + n] = fmaf(w0, a.z, fmaf(w1, bb.z, w2 * cc.z));
            ob[(size_t)(4*c + 3) * N + n] = fmaf(w0, a.w, fmaf(w1, bb.w, w2 * cc.w));
        }
    }
}

// ---------------------------------------------------------------------------
// Launch
// ---------------------------------------------------------------------------
extern "C" void kernel_launch(void* const* d_in, const int* in_sizes, int n_in,
                              void* d_out, int out_size) {
    const float* xyz0 = (const float*)d_in[0];
    const float* xyz1 = (const float*)d_in[1];
    const float* xyz2 = (const float*)d_in[2];
    const float* x0   = (const float*)d_in[3];
    const float* x1   = (const float*)d_in[4];
    const float* x2   = (const float*)d_in[5];
    float* out = (float*)d_out;

    int *cntA, *cntB, *qcntA, *qcntB, *cellA, *cellB, *qcellA, *qcellB;
    float4 *ptsA, *ptsB, *qA, *qB, *iwA, *iwB;
    unsigned short *permA, *permB;
    float* ip1;
    cudaGetSymbolAddress((void**)&cntA,   g_cntA);
    cudaGetSymbolAddress((void**)&cntB,   g_cntB);
    cudaGetSymbolAddress((void**)&qcntA,  g_qcntA);
    cudaGetSymbolAddress((void**)&qcntB,  g_qcntB);
    cudaGetSymbolAddress((void**)&cellA,  g_cellA);
    cudaGetSymbolAddress((void**)&cellB,  g_cellB);
    cudaGetSymbolAddress((void**)&qcellA, g_qcellA);
    cudaGetSymbolAddress((void**)&qcellB, g_qcellB);
    cudaGetSymbolAddress((void**)&ptsA,   g_ptsA);
    cudaGetSymbolAddress((void**)&ptsB,   g_ptsB);
    cudaGetSymbolAddress((void**)&qA,     g_qA);
    cudaGetSymbolAddress((void**)&qB,     g_qB);
    cudaGetSymbolAddress((void**)&permA,  g_permA);
    cudaGetSymbolAddress((void**)&permB,  g_permB);
    cudaGetSymbolAddress((void**)&iwA,    g_iwA);
    cudaGetSymbolAddress((void**)&iwB,    g_iwB);
    cudaGetSymbolAddress((void**)&ip1,    g_ip1);

    // 1) zero all cell counts
    k_zero4<<<(BATCH*CB + 255) / 256, 256>>>(cntA, cntB, qcntA, qcntB);

    // 2) bin everything
    k_bin4<<<(TOTPTS + 255) / 256, 256>>>(xyz0, xyz1, xyz2,
                                          cntA, cellA, cntB, cellB,
                                          qcntA, qcellA, qcntB, qcellB);

    // 3) prefix sums
    k_scan4<<<16, 1024>>>(cntA, cntB, qcntA, qcntB);

    // 4) scatter into cell order
    k_scatter4<<<(TOTPTS + 255) / 256, 256>>>(xyz0, xyz1, xyz2,
                                              cntA, cellA, cntB, cellB,
                                              qcntA, qcellA, qcntB, qcellB,
                                              ptsA, permA, ptsB, permB, qA, qB);

    // 5) merged 3-NN queries
    k_query_all<<<NBLKA + NBLKB, QBLK>>>(qA, cntA, ptsA, permA, iwA,
                                         qB, cntB, ptsB, permB, iwB);

    // 6) stage-1 interpolation
    {
        dim3 grid(D_IP1 / 16, BATCH);
        size_t smem = 16 * SA * sizeof(float);  // 32 KB
        k_gather<16><<<grid, 256, smem>>>(x2, D_IP1, SA, NA, iwA, ip1);
    }

    // 7) final interpolation rows [128,896) + fused x0 copy
    {
        cudaFuncSetAttribute(k_final<8>, cudaFuncAttributeMaxDynamicSharedMemorySize,
                             8 * 2048 * (int)sizeof(float));
        dim3 grid(FBLK_INTERP + FBLK_COPY, BATCH);
        size_t smem = 8 * 2048 * sizeof(float);  // 64 KB
        k_final<8><<<grid, 512, smem>>>(x0, x1, ip1, iwB, out);
    }
}

// round 10
// speedup vs baseline: 1.1450x; 1.1450x over previous
#include <cuda_runtime.h>
#include <cstdint>

// ---------------------------------------------------------------------------
// Problem constants
// ---------------------------------------------------------------------------
#define BATCH 4
// Level A: coarse = xyz2 (512 pts/b), queries = xyz1 (2048 pts/b)
#define SA 512
#define NA 2048
#define GA 16
#define CA (GA*GA*GA)
// Level B: coarse = xyz1 (2048 pts/b), queries = xyz0 (8192 pts/b)
#define SB 2048
#define NB 8192
#define GB 24
#define CB (GB*GB*GB)
#define BOUND 4.5f
#define HA (2.0f*BOUND/GA)     // 0.5625
#define HB (2.0f*BOUND/GB)     // 0.375

#define D_IP1 512
#define DOUT 896
#define NOUT 8192

// ---------------------------------------------------------------------------
// Device scratch (static: no runtime allocation allowed)
// ---------------------------------------------------------------------------
__device__ int            g_cntA[BATCH*CA];
__device__ int            g_cntB[BATCH*CB];
__device__ int            g_qcntA[BATCH*CA];
__device__ int            g_qcntB[BATCH*CB];
__device__ int            g_cellA[BATCH*SA];
__device__ int            g_cellB[BATCH*SB];
__device__ int            g_qcellA[BATCH*NA];
__device__ int            g_qcellB[BATCH*NB];
__device__ float4         g_ptsA[BATCH*SA];   // (x,y,z,Sb)
__device__ float4         g_ptsB[BATCH*SB];
__device__ unsigned short g_permA[BATCH*SA];  // sorted pos -> original idx
__device__ unsigned short g_permB[BATCH*SB];
__device__ float4         g_qA[BATCH*NA];     // sorted queries (x,y,z,orig)
__device__ float4         g_qB[BATCH*NB];
__device__ float4         g_iwA[BATCH*NA];    // {i0|i1<<16, i2, w0, w1}
__device__ float4         g_iwB[BATCH*NB];
__device__ float          g_ip1[(size_t)BATCH*D_IP1*NA];

// ---------------------------------------------------------------------------
// Helpers
// ---------------------------------------------------------------------------
__device__ __forceinline__ int cell1d(float x, float invh, int G) {
    int c = (int)floorf((x + BOUND) * invh);
    return min(max(c, 0), G - 1);
}

__device__ __forceinline__ unsigned ford(float f) {
    int ib = __float_as_int(f);
    return (unsigned)ib ^ (unsigned)((ib >> 31) | 0x80000000);
}
__device__ __forceinline__ float funord(unsigned o) {
    int ib = (o & 0x80000000u) ? (int)(o ^ 0x80000000u) : (int)~o;
    return __int_as_float(ib);
}

// ---------------------------------------------------------------------------
// Fused grid build
// ---------------------------------------------------------------------------
#define OFF1 (BATCH*SA)                    // 2048
#define OFF2 (OFF1 + BATCH*SB)             // 10240
#define OFF3 (OFF2 + BATCH*NA)             // 18432
#define TOTPTS (OFF3 + BATCH*NB)           // 51200

__global__ void k_zero4(int* __restrict__ a0, int* __restrict__ a1,
                        int* __restrict__ a2, int* __restrict__ a3) {
    int i = blockIdx.x * blockDim.x + threadIdx.x;
    if (i < BATCH*CA) { a0[i] = 0; a2[i] = 0; }
    if (i < BATCH*CB) { a1[i] = 0; a3[i] = 0; }
}

__global__ void k_bin4(const float* __restrict__ xyz0,
                       const float* __restrict__ xyz1,
                       const float* __restrict__ xyz2,
                       int* __restrict__ cntA,  int* __restrict__ cellA,
                       int* __restrict__ cntB,  int* __restrict__ cellB,
                       int* __restrict__ qcntA, int* __restrict__ qcellA,
                       int* __restrict__ qcntB, int* __restrict__ qcellB) {
    int gi = blockIdx.x * blockDim.x + threadIdx.x;
    if (gi >= TOTPTS) return;
    const float* xyz; int S, G; float invh; int *cnt, *cell; int i;
    if (gi < OFF1)      { i = gi;        xyz = xyz2; S = SA; G = GA; invh = 1.0f/HA; cnt = cntA;  cell = cellA;  }
    else if (gi < OFF2) { i = gi - OFF1; xyz = xyz1; S = SB; G = GB; invh = 1.0f/HB; cnt = cntB;  cell = cellB;  }
    else if (gi < OFF3) { i = gi - OFF2; xyz = xyz1; S = NA; G = GA; invh = 1.0f/HA; cnt = qcntA; cell = qcellA; }
    else                { i = gi - OFF3; xyz = xyz0; S = NB; G = GB; invh = 1.0f/HB; cnt = qcntB; cell = qcellB; }
    int b = i / S;
    const float* p = xyz + 3 * i;
    int cx = cell1d(p[0], invh, G);
    int cy = cell1d(p[1], invh, G);
    int cz = cell1d(p[2], invh, G);
    int c = (cz * G + cy) * G + cx;
    cell[i] = c;
    atomicAdd(&cnt[b * G * G * G + c], 1);
}

// Exclusive prefix sum; 16 blocks: [which*4 + b]
__global__ void k_scan4(int* __restrict__ cntA, int* __restrict__ cntB,
                        int* __restrict__ qcntA, int* __restrict__ qcntB) {
    __shared__ int ssum[1024];
    int which = blockIdx.x >> 2;
    int b = blockIdx.x & 3;
    int* base; int ncells;
    if (which == 0)      { base = cntA;  ncells = CA; }
    else if (which == 1) { base = cntB;  ncells = CB; }
    else if (which == 2) { base = qcntA; ncells = CA; }
    else                 { base = qcntB; ncells = CB; }
    int* a = base + b * ncells;
    int t = threadIdx.x;
    int chunk = (ncells + 1023) >> 10;
    int lo = t * chunk;
    int hi = min(lo + chunk, ncells);
    int s = 0;
    for (int i = lo; i < hi; ++i) s += a[i];
    ssum[t] = s;
    __syncthreads();
    for (int off = 1; off < 1024; off <<= 1) {
        int v = (t >= off) ? ssum[t - off] : 0;
        __syncthreads();
        ssum[t] += v;
        __syncthreads();
    }
    int run = (t == 0) ? 0 : ssum[t - 1];
    for (int i = lo; i < hi; ++i) { int c = a[i]; a[i] = run; run += c; }
}

__global__ void k_scatter4(const float* __restrict__ xyz0,
                           const float* __restrict__ xyz1,
                           const float* __restrict__ xyz2,
                           int* __restrict__ cntA,  const int* __restrict__ cellA,
                           int* __restrict__ cntB,  const int* __restrict__ cellB,
                           int* __restrict__ qcntA, const int* __restrict__ qcellA,
                           int* __restrict__ qcntB, const int* __restrict__ qcellB,
                           float4* __restrict__ ptsA, unsigned short* __restrict__ permA,
                           float4* __restrict__ ptsB, unsigned short* __restrict__ permB,
                           float4* __restrict__ qA, float4* __restrict__ qB) {
    int gi = blockIdx.x * blockDim.x + threadIdx.x;
    if (gi >= TOTPTS) return;
    if (gi < OFF2) {
        const float* xyz; int S, ncells; int* cnt; const int* cell;
        float4* pts; unsigned short* perm; int i;
        if (gi < OFF1) { i = gi;        xyz = xyz2; S = SA; ncells = CA; cnt = cntA; cell = cellA; pts = ptsA; perm = permA; }
        else           { i = gi - OFF1; xyz = xyz1; S = SB; ncells = CB; cnt = cntB; cell = cellB; pts = ptsB; perm = permB; }
        int b = i / S;
        int s = i - b * S;
        int pos = atomicAdd(&cnt[b * ncells + cell[i]], 1);
        const float* p = xyz + 3 * i;
        float x = p[0], y = p[1], z = p[2];
        float Sb = __fadd_rn(__fadd_rn(__fmul_rn(x, x), __fmul_rn(y, y)), __fmul_rn(z, z));
        pts[b * S + pos] = make_float4(x, y, z, Sb);
        perm[b * S + pos] = (unsigned short)s;
    } else {
        const float* xyz; int S, ncells; int* cnt; const int* cell; float4* q; int i;
        if (gi < OFF3) { i = gi - OFF2; xyz = xyz1; S = NA; ncells = CA; cnt = qcntA; cell = qcellA; q = qA; }
        else           { i = gi - OFF3; xyz = xyz0; S = NB; ncells = CB; cnt = qcntB; cell = qcellB; q = qB; }
        int b = i / S;
        int s = i - b * S;
        int pos = atomicAdd(&cnt[b * ncells + cell[i]], 1);
        const float* p = xyz + 3 * i;
        q[b * S + pos] = make_float4(p[0], p[1], p[2], __int_as_float(s));
    }
}

// ---------------------------------------------------------------------------
// 3-NN query. Distances computed EXACTLY like the reference:
//   d = (Sa + Sb) - 2*dot,  dot = fma(a2,b2, fma(a1,b1, RN(a0*b0)))
// Top-3 as 64-bit keys (full d bits | sorted pos); rare-branch insertion.
// ---------------------------------------------------------------------------
__device__ __forceinline__ void scan_range(
    const float4* __restrict__ pp, int s0, int s1,
    float px, float py, float pz, float Sa,
    unsigned long long& k1, unsigned long long& k2, unsigned long long& k3)
{
    for (int i = s0; i < s1; ++i) {
        float4 Q = __ldg(pp + i);
        float dot = __fmaf_rn(pz, Q.z, __fmaf_rn(py, Q.y, __fmul_rn(px, Q.x)));
        float d = __fsub_rn(__fadd_rn(Sa, Q.w), __fmul_rn(2.0f, dot));
        unsigned long long key = ((unsigned long long)ford(d) << 32) | (unsigned)i;
        if (key < k3) {
            unsigned long long t = min(k2, key);
            k3 = max(k2, key);
            k2 = t;
            t = min(k1, k2);
            k2 = max(k1, k2);
            k1 = t;
        }
    }
}

__device__ __forceinline__ void run_query(
    const float4* __restrict__ qs, int N,
    const int* __restrict__ cnt, const float4* __restrict__ pts,
    const unsigned short* __restrict__ perm, int S,
    int G, float h, float invh,
    float4* __restrict__ iw, int gid)
{
    float4 q4 = qs[gid];
    int b = gid / N;
    float px = q4.x, py = q4.y, pz = q4.z;
    int orig = __float_as_int(q4.w);
    float Sa = __fadd_rn(__fadd_rn(__fmul_rn(px, px), __fmul_rn(py, py)),
                         __fmul_rn(pz, pz));
    int cx = cell1d(px, invh, G);
    int cy = cell1d(py, invh, G);
    int cz = cell1d(pz, invh, G);
    const int*    cc = cnt + b * G * G * G;
    const float4* pp = pts + b * S;

    unsigned long long k1 = ~0ull, k2 = ~0ull, k3 = ~0ull;

    for (int r = 0; r < G; ++r) {
        int zlo = max(cz - r, 0), zhi = min(cz + r, G - 1);
        int ylo = max(cy - r, 0), yhi = min(cy + r, G - 1);
        int xlo = max(cx - r, 0), xhi = min(cx + r, G - 1);
        for (int z = zlo; z <= zhi; ++z) {
            bool zface = (z == cz - r) || (z == cz + r);
            for (int y = ylo; y <= yhi; ++y) {
                bool face = zface || (y == cy - r) || (y == cy + r);
                int rowbase = (z * G + y) * G;
                if (face) {
                    int c0 = rowbase + xlo, c1 = rowbase + xhi;
                    int s0 = (c0 == 0) ? 0 : cc[c0 - 1];
                    int s1 = cc[c1];
                    scan_range(pp, s0, s1, px, py, pz, Sa, k1, k2, k3);
                } else {
                    int xa = cx - r, xb_ = cx + r;
                    if (xa >= 0) {
                        int c = rowbase + xa;
                        int s0 = (c == 0) ? 0 : cc[c - 1];
                        scan_range(pp, s0, cc[c], px, py, pz, Sa, k1, k2, k3);
                    }
                    if (xb_ < G) {
                        int c = rowbase + xb_;
                        scan_range(pp, cc[c - 1], cc[c], px, py, pz, Sa, k1, k2, k3);
                    }
                }
            }
        }
        if (k3 != ~0ull) {
            float rb = r * h;
            unsigned thr = ford(rb * rb - 1e-5f);
            if ((unsigned)(k3 >> 32) <= thr) break;
        }
    }

    float d0 = funord((unsigned)(k1 >> 32));
    float d1 = funord((unsigned)(k2 >> 32));
    float d2 = funord((unsigned)(k3 >> 32));
    float r0 = __frcp_rn(__fadd_rn(d0, 1e-8f));
    float r1 = __frcp_rn(__fadd_rn(d1, 1e-8f));
    float r2 = __frcp_rn(__fadd_rn(d2, 1e-8f));
    float s  = __fadd_rn(__fadd_rn(r0, r1), r2);
    float w0 = __fdiv_rn(r0, s);
    float w1 = __fdiv_rn(r1, s);

    const unsigned short* pm = perm + b * S;
    int i0 = pm[(unsigned)(k1 & 0xFFFFFFFFu)];
    int i1 = pm[(unsigned)(k2 & 0xFFFFFFFFu)];
    int i2 = pm[(unsigned)(k3 & 0xFFFFFFFFu)];

    float4 o;
    o.x = __int_as_float(i0 | (i1 << 16));
    o.y = __int_as_float(i2);
    o.z = w0;
    o.w = w1;   // w2 = 1 - w0 - w1
    iw[b * N + orig] = o;
}

#define QBLK 64
#define NBLKA ((BATCH*NA)/QBLK)   // 128
#define NBLKB ((BATCH*NB)/QBLK)   // 512

__global__ void k_query_all(
    const float4* __restrict__ qA, const int* __restrict__ cntA,
    const float4* __restrict__ ptsA, const unsigned short* __restrict__ permA,
    float4* __restrict__ iwA,
    const float4* __restrict__ qB, const int* __restrict__ cntB,
    const float4* __restrict__ ptsB, const unsigned short* __restrict__ permB,
    float4* __restrict__ iwB)
{
    if (blockIdx.x < NBLKA) {
        int gid = blockIdx.x * QBLK + threadIdx.x;
        run_query(qA, NA, cntA, ptsA, permA, SA, GA, HA, 1.0f / HA, iwA, gid);
    } else {
        int gid = (blockIdx.x - NBLKA) * QBLK + threadIdx.x;
        run_query(qB, NB, cntB, ptsB, permB, SB, GB, HB, 1.0f / HB, iwB, gid);
    }
}

// ---------------------------------------------------------------------------
// Stage-1 interpolation: ip1[b][d][n] = sum_k w_k * x2[b][d][idx_k]
// Row-major smem tiles (sm[d][s]) -- measured best layout.
// ---------------------------------------------------------------------------
template <int DT>
__global__ void k_gather(const float* __restrict__ feat, int D, int S, int N,
                         const float4* __restrict__ iw, float* __restrict__ out) {
    extern __shared__ float sm[];
    int b = blockIdx.y;
    int d0 = blockIdx.x * DT;
    const float4* fb = (const float4*)(feat + ((size_t)b * D + d0) * S);
    int tot4 = DT * S / 4;
    for (int i = threadIdx.x; i < tot4; i += blockDim.x)
        ((float4*)sm)[i] = fb[i];
    __syncthreads();

    const float4* iwb = iw + b * N;
    float* ob = out + ((size_t)b * D + d0) * N;
    for (int n = threadIdx.x; n < N; n += blockDim.x) {
        float4 v = iwb[n];
        unsigned ii = (unsigned)__float_as_int(v.x);
        int i0 = ii & 0xFFFF, i1 = ii >> 16;
        int i2 = __float_as_int(v.y);
        float w0 = v.z, w1 = v.w, w2 = 1.0f - w0 - w1;
#pragma unroll
        for (int d = 0; d < DT; ++d) {
            const float* row = sm + d * S;
            ob[(size_t)d * N + n] = fmaf(w0, row[i0], fmaf(w1, row[i1], w2 * row[i2]));
        }
    }
}

// ---------------------------------------------------------------------------
// Final stage-2 interpolation into rows [128,896); x0 copy fused as extra
// blocks (pure float4 copy, no smem interaction).
// ---------------------------------------------------------------------------
#define FBLK_INTERP 96    // (896-128)/8
#define FBLK_COPY 16
template <int DT>
__global__ void k_final(const float* __restrict__ x0,
                        const float* __restrict__ x1, const float* __restrict__ ip1,
                        const float4* __restrict__ iw, float* __restrict__ out) {
    extern __shared__ float sm[];
    const int S = 2048, N = 8192;
    int b = blockIdx.y;

    if (blockIdx.x >= FBLK_INTERP) {
        // pure copy of x0 rows [0,128)
        int cb = blockIdx.x - FBLK_INTERP;
        const int per_b = 128 * 8192 / 4;             // 262144 float4
        const int per_blk = per_b / FBLK_COPY;        // 16384
        const float4* s = (const float4*)(x0 + (size_t)b * 128 * 8192);
        float4*       d = (float4*)(out + (size_t)b * DOUT * 8192);
        int lo = cb * per_blk;
        for (int i = lo + threadIdx.x; i < lo + per_blk; i += blockDim.x)
            d[i] = s[i];
        return;
    }

    int d0 = 128 + blockIdx.x * DT;

    const int rows4 = S / 4;  // 512
    for (int i = threadIdx.x; i < DT * rows4; i += blockDim.x) {
        int j = i >> 9;
        int col = i & 511;
        int d = d0 + j;
        const float* src = (d < 384)
            ? (x1  + ((size_t)b * 256 + (d - 128)) * S)
            : (ip1 + ((size_t)b * 512 + (d - 384)) * S);
        ((float4*)sm)[i] = ((const float4*)src)[col];
    }
    __syncthreads();

    const float4* iwb = iw + b * N;
    float* ob = out + ((size_t)b * DOUT + d0) * N;
    for (int n = threadIdx.x; n < N; n += blockDim.x) {
        float4 v = iwb[n];
        unsigned ii = (unsigned)__float_as_int(v.x);
        int i0 = ii & 0xFFFF, i1 = ii >> 16;
        int i2 = __float_as_int(v.y);
        float w0 = v.z, w1 = v.w, w2 = 1.0f - w0 - w1;
#pragma unroll
        for (int d = 0; d < DT; ++d) {
            const float* row = sm + d * S;
            ob[(size_t)d * N + n] = fmaf(w0, row[i0], fmaf(w1, row[i1], w2 * row[i2]));
        }
    }
}

// ---------------------------------------------------------------------------
// Launch
// ---------------------------------------------------------------------------
extern "C" void kernel_launch(void* const* d_in, const int* in_sizes, int n_in,
                              void* d_out, int out_size) {
    const float* xyz0 = (const float*)d_in[0];
    const float* xyz1 = (const float*)d_in[1];
    const float* xyz2 = (const float*)d_in[2];
    const float* x0   = (const float*)d_in[3];
    const float* x1   = (const float*)d_in[4];
    const float* x2   = (const float*)d_in[5];
    float* out = (float*)d_out;

    int *cntA, *cntB, *qcntA, *qcntB, *cellA, *cellB, *qcellA, *qcellB;
    float4 *ptsA, *ptsB, *qA, *qB, *iwA, *iwB;
    unsigned short *permA, *permB;
    float* ip1;
    cudaGetSymbolAddress((void**)&cntA,   g_cntA);
    cudaGetSymbolAddress((void**)&cntB,   g_cntB);
    cudaGetSymbolAddress((void**)&qcntA,  g_qcntA);
    cudaGetSymbolAddress((void**)&qcntB,  g_qcntB);
    cudaGetSymbolAddress((void**)&cellA,  g_cellA);
    cudaGetSymbolAddress((void**)&cellB,  g_cellB);
    cudaGetSymbolAddress((void**)&qcellA, g_qcellA);
    cudaGetSymbolAddress((void**)&qcellB, g_qcellB);
    cudaGetSymbolAddress((void**)&ptsA,   g_ptsA);
    cudaGetSymbolAddress((void**)&ptsB,   g_ptsB);
    cudaGetSymbolAddress((void**)&qA,     g_qA);
    cudaGetSymbolAddress((void**)&qB,     g_qB);
    cudaGetSymbolAddress((void**)&permA,  g_permA);
    cudaGetSymbolAddress((void**)&permB,  g_permB);
    cudaGetSymbolAddress((void**)&iwA,    g_iwA);
    cudaGetSymbolAddress((void**)&iwB,    g_iwB);
    cudaGetSymbolAddress((void**)&ip1,    g_ip1);

    // 1) zero all cell counts
    k_zero4<<<(BATCH*CB + 255) / 256, 256>>>(cntA, cntB, qcntA, qcntB);

    // 2) bin everything
    k_bin4<<<(TOTPTS + 255) / 256, 256>>>(xyz0, xyz1, xyz2,
                                          cntA, cellA, cntB, cellB,
                                          qcntA, qcellA, qcntB, qcellB);

    // 3) prefix sums
    k_scan4<<<16, 1024>>>(cntA, cntB, qcntA, qcntB);

    // 4) scatter into cell order
    k_scatter4<<<(TOTPTS + 255) / 256, 256>>>(xyz0, xyz1, xyz2,
                                              cntA, cellA, cntB, cellB,
                                              qcntA, qcellA, qcntB, qcellB,
                                              ptsA, permA, ptsB, permB, qA, qB);

    // 5) merged 3-NN queries
    k_query_all<<<NBLKA + NBLKB, QBLK>>>(qA, cntA, ptsA, permA, iwA,
                                         qB, cntB, ptsB, permB, iwB);

    // 6) stage-1 interpolation
    {
        dim3 grid(D_IP1 / 16, BATCH);
        size_t smem = 16 * SA * sizeof(float);  // 32 KB
        k_gather<16><<<grid, 256, smem>>>(x2, D_IP1, SA, NA, iwA, ip1);
    }

    // 7) final interpolation rows [128,896) + fused x0 copy
    {
        cudaFuncSetAttribute(k_final<8>, cudaFuncAttributeMaxDynamicSharedMemorySize,
                             8 * 2048 * (int)sizeof(float));
        dim3 grid(FBLK_INTERP + FBLK_COPY, BATCH);
        size_t smem = 8 * 2048 * sizeof(float);  // 64 KB
        k_final<8><<<grid, 512, smem>>>(x0, x1, ip1, iwB, out);
    }
}

// round 16
// speedup vs baseline: 1.7017x; 1.4862x over previous
#include <cuda_runtime.h>
#include <cstdint>

// ---------------------------------------------------------------------------
// Problem constants
// ---------------------------------------------------------------------------
#define BATCH 4
// Level A: coarse = xyz2 (512 pts/b), queries = xyz1 (2048 pts/b)
#define SA 512
#define NA 2048
#define GA 16
#define CA (GA*GA*GA)
// Level B: coarse = xyz1 (2048 pts/b), queries = xyz0 (8192 pts/b)
#define SB 2048
#define NB 8192
#define GB 24
#define CB (GB*GB*GB)
#define BOUND 4.5f
#define HA (2.0f*BOUND/GA)     // 0.5625
#define HB (2.0f*BOUND/GB)     // 0.375

#define D_IP1 512
#define DOUT 896
#define NOUT 8192

// ---------------------------------------------------------------------------
// Device scratch (static: no runtime allocation allowed)
// ---------------------------------------------------------------------------
__device__ int            g_cntA[BATCH*CA];
__device__ int            g_cntB[BATCH*CB];
__device__ int            g_qcntA[BATCH*CA];
__device__ int            g_qcntB[BATCH*CB];
__device__ int            g_cellA[BATCH*SA];
__device__ int            g_cellB[BATCH*SB];
__device__ int            g_qcellA[BATCH*NA];
__device__ int            g_qcellB[BATCH*NB];
__device__ float4         g_ptsA[BATCH*SA];   // (x,y,z,Sb)
__device__ float4         g_ptsB[BATCH*SB];
__device__ unsigned short g_permA[BATCH*SA];  // sorted pos -> original idx
__device__ unsigned short g_permB[BATCH*SB];
__device__ float4         g_qA[BATCH*NA];     // sorted queries (x,y,z,orig)
__device__ float4         g_qB[BATCH*NB];
__device__ float4         g_iwA[BATCH*NA];    // {i0|i1<<16, i2, w0, w1}
__device__ float4         g_iwB[BATCH*NB];
__device__ float          g_ip1[(size_t)BATCH*D_IP1*NA];

// ---------------------------------------------------------------------------
// Helpers
// ---------------------------------------------------------------------------
__device__ __forceinline__ int cell1d(float x, float invh, int G) {
    int c = (int)floorf((x + BOUND) * invh);
    return min(max(c, 0), G - 1);
}

__device__ __forceinline__ unsigned ford(float f) {
    int ib = __float_as_int(f);
    return (unsigned)ib ^ (unsigned)((ib >> 31) | 0x80000000);
}
__device__ __forceinline__ float funord(unsigned o) {
    int ib = (o & 0x80000000u) ? (int)(o ^ 0x80000000u) : (int)~o;
    return __int_as_float(ib);
}

// ---------------------------------------------------------------------------
// Fused grid build
// ---------------------------------------------------------------------------
#define OFF1 (BATCH*SA)                    // 2048
#define OFF2 (OFF1 + BATCH*SB)             // 10240
#define OFF3 (OFF2 + BATCH*NA)             // 18432
#define TOTPTS (OFF3 + BATCH*NB)           // 51200

__global__ void k_zero4(int* __restrict__ a0, int* __restrict__ a1,
                        int* __restrict__ a2, int* __restrict__ a3) {
    int i = blockIdx.x * blockDim.x + threadIdx.x;
    // a0,a2: BATCH*CA ints; a1,a3: BATCH*CB ints
    if (i < BATCH*CA) { a0[i] = 0; a2[i] = 0; }
    if (i < BATCH*CB) { a1[i] = 0; a3[i] = 0; }
}

__global__ void k_bin4(const float* __restrict__ xyz0,
                       const float* __restrict__ xyz1,
                       const float* __restrict__ xyz2,
                       int* __restrict__ cntA,  int* __restrict__ cellA,
                       int* __restrict__ cntB,  int* __restrict__ cellB,
                       int* __restrict__ qcntA, int* __restrict__ qcellA,
                       int* __restrict__ qcntB, int* __restrict__ qcellB) {
    int gi = blockIdx.x * blockDim.x + threadIdx.x;
    if (gi >= TOTPTS) return;
    const float* xyz; int S, G; float invh; int *cnt, *cell; int i;
    if (gi < OFF1)      { i = gi;        xyz = xyz2; S = SA; G = GA; invh = 1.0f/HA; cnt = cntA;  cell = cellA;  }
    else if (gi < OFF2) { i = gi - OFF1; xyz = xyz1; S = SB; G = GB; invh = 1.0f/HB; cnt = cntB;  cell = cellB;  }
    else if (gi < OFF3) { i = gi - OFF2; xyz = xyz1; S = NA; G = GA; invh = 1.0f/HA; cnt = qcntA; cell = qcellA; }
    else                { i = gi - OFF3; xyz = xyz0; S = NB; G = GB; invh = 1.0f/HB; cnt = qcntB; cell = qcellB; }
    int b = i / S;
    const float* p = xyz + 3 * i;
    int cx = cell1d(p[0], invh, G);
    int cy = cell1d(p[1], invh, G);
    int cz = cell1d(p[2], invh, G);
    int c = (cz * G + cy) * G + cx;
    cell[i] = c;
    atomicAdd(&cnt[b * G * G * G + c], 1);
}

// Exclusive prefix sum; 16 blocks: [which*4 + b]
__global__ void k_scan4(int* __restrict__ cntA, int* __restrict__ cntB,
                        int* __restrict__ qcntA, int* __restrict__ qcntB) {
    __shared__ int ssum[1024];
    int which = blockIdx.x >> 2;
    int b = blockIdx.x & 3;
    int* base; int ncells;
    if (which == 0)      { base = cntA;  ncells = CA; }
    else if (which == 1) { base = cntB;  ncells = CB; }
    else if (which == 2) { base = qcntA; ncells = CA; }
    else                 { base = qcntB; ncells = CB; }
    int* a = base + b * ncells;
    int t = threadIdx.x;
    int chunk = (ncells + 1023) >> 10;
    int lo = t * chunk;
    int hi = min(lo + chunk, ncells);
    int s = 0;
    for (int i = lo; i < hi; ++i) s += a[i];
    ssum[t] = s;
    __syncthreads();
    for (int off = 1; off < 1024; off <<= 1) {
        int v = (t >= off) ? ssum[t - off] : 0;
        __syncthreads();
        ssum[t] += v;
        __syncthreads();
    }
    int run = (t == 0) ? 0 : ssum[t - 1];
    for (int i = lo; i < hi; ++i) { int c = a[i]; a[i] = run; run += c; }
}

__global__ void k_scatter4(const float* __restrict__ xyz0,
                           const float* __restrict__ xyz1,
                           const float* __restrict__ xyz2,
                           int* __restrict__ cntA,  const int* __restrict__ cellA,
                           int* __restrict__ cntB,  const int* __restrict__ cellB,
                           int* __restrict__ qcntA, const int* __restrict__ qcellA,
                           int* __restrict__ qcntB, const int* __restrict__ qcellB,
                           float4* __restrict__ ptsA, unsigned short* __restrict__ permA,
                           float4* __restrict__ ptsB, unsigned short* __restrict__ permB,
                           float4* __restrict__ qA, float4* __restrict__ qB) {
    int gi = blockIdx.x * blockDim.x + threadIdx.x;
    if (gi >= TOTPTS) return;
    if (gi < OFF2) {
        const float* xyz; int S, ncells; int* cnt; const int* cell;
        float4* pts; unsigned short* perm; int i;
        if (gi < OFF1) { i = gi;        xyz = xyz2; S = SA; ncells = CA; cnt = cntA; cell = cellA; pts = ptsA; perm = permA; }
        else           { i = gi - OFF1; xyz = xyz1; S = SB; ncells = CB; cnt = cntB; cell = cellB; pts = ptsB; perm = permB; }
        int b = i / S;
        int s = i - b * S;
        int pos = atomicAdd(&cnt[b * ncells + cell[i]], 1);
        const float* p = xyz + 3 * i;
        float x = p[0], y = p[1], z = p[2];
        float Sb = __fadd_rn(__fadd_rn(__fmul_rn(x, x), __fmul_rn(y, y)), __fmul_rn(z, z));
        pts[b * S + pos] = make_float4(x, y, z, Sb);
        perm[b * S + pos] = (unsigned short)s;
    } else {
        const float* xyz; int S, ncells; int* cnt; const int* cell; float4* q; int i;
        if (gi < OFF3) { i = gi - OFF2; xyz = xyz1; S = NA; ncells = CA; cnt = qcntA; cell = qcellA; q = qA; }
        else           { i = gi - OFF3; xyz = xyz0; S = NB; ncells = CB; cnt = qcntB; cell = qcellB; q = qB; }
        int b = i / S;
        int s = i - b * S;
        int pos = atomicAdd(&cnt[b * ncells + cell[i]], 1);
        const float* p = xyz + 3 * i;
        q[b * S + pos] = make_float4(p[0], p[1], p[2], __int_as_float(s));
    }
}

// ---------------------------------------------------------------------------
// 3-NN query. Distances computed EXACTLY like the reference:
//   d = (Sa + Sb) - 2*dot,  dot = fma(a2,b2, fma(a1,b1, RN(a0*b0)))
// Top-3 as 64-bit keys (full d bits | sorted pos); rare-branch insertion.
// ---------------------------------------------------------------------------
__device__ __forceinline__ void scan_range(
    const float4* __restrict__ pp, int s0, int s1,
    float px, float py, float pz, float Sa,
    unsigned long long& k1, unsigned long long& k2, unsigned long long& k3)
{
    for (int i = s0; i < s1; ++i) {
        float4 Q = __ldg(pp + i);
        float dot = __fmaf_rn(pz, Q.z, __fmaf_rn(py, Q.y, __fmul_rn(px, Q.x)));
        float d = __fsub_rn(__fadd_rn(Sa, Q.w), __fmul_rn(2.0f, dot));
        unsigned long long key = ((unsigned long long)ford(d) << 32) | (unsigned)i;
        if (key < k3) {
            unsigned long long t = min(k2, key);
            k3 = max(k2, key);
            k2 = t;
            t = min(k1, k2);
            k2 = max(k1, k2);
            k1 = t;
        }
    }
}

__device__ __forceinline__ void run_query(
    const float4* __restrict__ qs, int N,
    const int* __restrict__ cnt, const float4* __restrict__ pts,
    const unsigned short* __restrict__ perm, int S,
    int G, float h, float invh,
    float4* __restrict__ iw, int gid)
{
    float4 q4 = qs[gid];
    int b = gid / N;
    float px = q4.x, py = q4.y, pz = q4.z;
    int orig = __float_as_int(q4.w);
    float Sa = __fadd_rn(__fadd_rn(__fmul_rn(px, px), __fmul_rn(py, py)),
                         __fmul_rn(pz, pz));
    int cx = cell1d(px, invh, G);
    int cy = cell1d(py, invh, G);
    int cz = cell1d(pz, invh, G);
    const int*    cc = cnt + b * G * G * G;
    const float4* pp = pts + b * S;

    unsigned long long k1 = ~0ull, k2 = ~0ull, k3 = ~0ull;

    for (int r = 0; r < G; ++r) {
        int zlo = max(cz - r, 0), zhi = min(cz + r, G - 1);
        int ylo = max(cy - r, 0), yhi = min(cy + r, G - 1);
        int xlo = max(cx - r, 0), xhi = min(cx + r, G - 1);
        for (int z = zlo; z <= zhi; ++z) {
            bool zface = (z == cz - r) || (z == cz + r);
            for (int y = ylo; y <= yhi; ++y) {
                bool face = zface || (y == cy - r) || (y == cy + r);
                int rowbase = (z * G + y) * G;
                if (face) {
                    int c0 = rowbase + xlo, c1 = rowbase + xhi;
                    int s0 = (c0 == 0) ? 0 : cc[c0 - 1];
                    int s1 = cc[c1];
                    scan_range(pp, s0, s1, px, py, pz, Sa, k1, k2, k3);
                } else {
                    int xa = cx - r, xb_ = cx + r;
                    if (xa >= 0) {
                        int c = rowbase + xa;
                        int s0 = (c == 0) ? 0 : cc[c - 1];
                        scan_range(pp, s0, cc[c], px, py, pz, Sa, k1, k2, k3);
                    }
                    if (xb_ < G) {
                        int c = rowbase + xb_;
                        scan_range(pp, cc[c - 1], cc[c], px, py, pz, Sa, k1, k2, k3);
                    }
                }
            }
        }
        if (k3 != ~0ull) {
            float rb = r * h;
            unsigned thr = ford(rb * rb - 1e-5f);
            if ((unsigned)(k3 >> 32) <= thr) break;
        }
    }

    float d0 = funord((unsigned)(k1 >> 32));
    float d1 = funord((unsigned)(k2 >> 32));
    float d2 = funord((unsigned)(k3 >> 32));
    float r0 = __frcp_rn(__fadd_rn(d0, 1e-8f));
    float r1 = __frcp_rn(__fadd_rn(d1, 1e-8f));
    float r2 = __frcp_rn(__fadd_rn(d2, 1e-8f));
    float s  = __fadd_rn(__fadd_rn(r0, r1), r2);
    float w0 = __fdiv_rn(r0, s);
    float w1 = __fdiv_rn(r1, s);

    const unsigned short* pm = perm + b * S;
    int i0 = pm[(unsigned)(k1 & 0xFFFFFFFFu)];
    int i1 = pm[(unsigned)(k2 & 0xFFFFFFFFu)];
    int i2 = pm[(unsigned)(k3 & 0xFFFFFFFFu)];

    float4 o;
    o.x = __int_as_float(i0 | (i1 << 16));
    o.y = __int_as_float(i2);
    o.z = w0;
    o.w = w1;   // w2 = 1 - w0 - w1
    iw[b * N + orig] = o;
}

#define QBLK 64
#define NBLKA ((BATCH*NA)/QBLK)   // 128
#define NBLKB ((BATCH*NB)/QBLK)   // 512

__global__ void k_query_all(
    const float4* __restrict__ qA, const int* __restrict__ cntA,
    const float4* __restrict__ ptsA, const unsigned short* __restrict__ permA,
    float4* __restrict__ iwA,
    const float4* __restrict__ qB, const int* __restrict__ cntB,
    const float4* __restrict__ ptsB, const unsigned short* __restrict__ permB,
    float4* __restrict__ iwB)
{
    if (blockIdx.x < NBLKA) {
        int gid = blockIdx.x * QBLK + threadIdx.x;
        run_query(qA, NA, cntA, ptsA, permA, SA, GA, HA, 1.0f / HA, iwA, gid);
    } else {
        int gid = (blockIdx.x - NBLKA) * QBLK + threadIdx.x;
        run_query(qB, NB, cntB, ptsB, permB, SB, GB, HB, 1.0f / HB, iwB, gid);
    }
}

// ---------------------------------------------------------------------------
// Stage-1 interpolation: ip1[b][d][n] = sum_k w_k * x2[b][d][idx_k]
// ---------------------------------------------------------------------------
template <int DT>
__global__ void k_gather(const float* __restrict__ feat, int D, int S, int N,
                         const float4* __restrict__ iw, float* __restrict__ out) {
    extern __shared__ float sm[];
    int b = blockIdx.y;
    int d0 = blockIdx.x * DT;
    const float4* fb = (const float4*)(feat + ((size_t)b * D + d0) * S);
    int tot4 = DT * S / 4;
    for (int i = threadIdx.x; i < tot4; i += blockDim.x)
        ((float4*)sm)[i] = fb[i];
    __syncthreads();

    const float4* iwb = iw + b * N;
    float* ob = out + ((size_t)b * D + d0) * N;
    for (int n = threadIdx.x; n < N; n += blockDim.x) {
        float4 v = iwb[n];
        unsigned ii = (unsigned)__float_as_int(v.x);
        int i0 = ii & 0xFFFF, i1 = ii >> 16;
        int i2 = __float_as_int(v.y);
        float w0 = v.z, w1 = v.w, w2 = 1.0f - w0 - w1;
#pragma unroll
        for (int d = 0; d < DT; ++d) {
            const float* row = sm + d * S;
            ob[(size_t)d * N + n] = fmaf(w0, row[i0], fmaf(w1, row[i1], w2 * row[i2]));
        }
    }
}

// ---------------------------------------------------------------------------
// Final stage-2 interpolation into output rows [128, 896).
// ---------------------------------------------------------------------------
template <int DT>
__global__ void k_final(const float* __restrict__ x1, const float* __restrict__ ip1,
                        const float4* __restrict__ iw, float* __restrict__ out) {
    extern __shared__ float sm[];
    const int S = 2048, N = 8192;
    int b = blockIdx.y;
    int d0 = 128 + blockIdx.x * DT;

    const int rows4 = S / 4;  // 512
    for (int i = threadIdx.x; i < DT * rows4; i += blockDim.x) {
        int j = i >> 9;
        int col = i & 511;
        int d = d0 + j;
        const float* src = (d < 384)
            ? (x1  + ((size_t)b * 256 + (d - 128)) * S)
            : (ip1 + ((size_t)b * 512 + (d - 384)) * S);
        ((float4*)sm)[i] = ((const float4*)src)[col];
    }
    __syncthreads();

    const float4* iwb = iw + b * N;
    float* ob = out + ((size_t)b * DOUT + d0) * N;
    for (int n = threadIdx.x; n < N; n += blockDim.x) {
        float4 v = iwb[n];
        unsigned ii = (unsigned)__float_as_int(v.x);
        int i0 = ii & 0xFFFF, i1 = ii >> 16;
        int i2 = __float_as_int(v.y);
        float w0 = v.z, w1 = v.w, w2 = 1.0f - w0 - w1;
#pragma unroll
        for (int d = 0; d < DT; ++d) {
            const float* row = sm + d * S;
            ob[(size_t)d * N + n] = fmaf(w0, row[i0], fmaf(w1, row[i1], w2 * row[i2]));
        }
    }
}

// Copy x0 into output rows [0, 128).
__global__ void k_copy(const float* __restrict__ x0, float* __restrict__ out) {
    const int per_b = 128 * 8192 / 4;
    int i = blockIdx.x * blockDim.x + threadIdx.x;
    if (i >= BATCH * per_b) return;
    int b = i / per_b;
    int j = i - b * per_b;
    const float4* s = (const float4*)(x0 + (size_t)b * 128 * 8192);
    float4*       d = (float4*)(out + (size_t)b * DOUT * 8192);
    d[j] = s[j];
}

// ---------------------------------------------------------------------------
// Launch
// ---------------------------------------------------------------------------
extern "C" void kernel_launch(void* const* d_in, const int* in_sizes, int n_in,
                              void* d_out, int out_size) {
    const float* xyz0 = (const float*)d_in[0];
    const float* xyz1 = (const float*)d_in[1];
    const float* xyz2 = (const float*)d_in[2];
    const float* x0   = (const float*)d_in[3];
    const float* x1   = (const float*)d_in[4];
    const float* x2   = (const float*)d_in[5];
    float* out = (float*)d_out;

    int *cntA, *cntB, *qcntA, *qcntB, *cellA, *cellB, *qcellA, *qcellB;
    float4 *ptsA, *ptsB, *qA, *qB, *iwA, *iwB;
    unsigned short *permA, *permB;
    float* ip1;
    cudaGetSymbolAddress((void**)&cntA,   g_cntA);
    cudaGetSymbolAddress((void**)&cntB,   g_cntB);
    cudaGetSymbolAddress((void**)&qcntA,  g_qcntA);
    cudaGetSymbolAddress((void**)&qcntB,  g_qcntB);
    cudaGetSymbolAddress((void**)&cellA,  g_cellA);
    cudaGetSymbolAddress((void**)&cellB,  g_cellB);
    cudaGetSymbolAddress((void**)&qcellA, g_qcellA);
    cudaGetSymbolAddress((void**)&qcellB, g_qcellB);
    cudaGetSymbolAddress((void**)&ptsA,   g_ptsA);
    cudaGetSymbolAddress((void**)&ptsB,   g_ptsB);
    cudaGetSymbolAddress((void**)&qA,     g_qA);
    cudaGetSymbolAddress((void**)&qB,     g_qB);
    cudaGetSymbolAddress((void**)&permA,  g_permA);
    cudaGetSymbolAddress((void**)&permB,  g_permB);
    cudaGetSymbolAddress((void**)&iwA,    g_iwA);
    cudaGetSymbolAddress((void**)&iwB,    g_iwB);
    cudaGetSymbolAddress((void**)&ip1,    g_ip1);

    // 1) zero all cell counts (one launch)
    k_zero4<<<(BATCH*CB + 255) / 256, 256>>>(cntA, cntB, qcntA, qcntB);

    // 2) bin everything (one launch)
    k_bin4<<<(TOTPTS + 255) / 256, 256>>>(xyz0, xyz1, xyz2,
                                          cntA, cellA, cntB, cellB,
                                          qcntA, qcellA, qcntB, qcellB);

    // 3) prefix sums (one launch, 16 blocks)
    k_scan4<<<16, 1024>>>(cntA, cntB, qcntA, qcntB);

    // 4) scatter into cell order (one launch)
    k_scatter4<<<(TOTPTS + 255) / 256, 256>>>(xyz0, xyz1, xyz2,
                                              cntA, cellA, cntB, cellB,
                                              qcntA, qcellA, qcntB, qcellB,
                                              ptsA, permA, ptsB, permB, qA, qB);

    // 5) copy x0 rows (independent; early so ncu -s 5 lands on the query kernel)
    k_copy<<<(BATCH * 128 * 8192 / 4 + 255) / 256, 256>>>(x0, out);

    // 6) merged 3-NN queries (both levels in one launch)
    k_query_all<<<NBLKA + NBLKB, QBLK>>>(qA, cntA, ptsA, permA, iwA,
                                         qB, cntB, ptsB, permB, iwB);

    // 7) stage-1 interpolation: g_ip1[b][512][2048] from x2
    {
        dim3 grid(D_IP1 / 16, BATCH);
        size_t smem = 16 * SA * sizeof(float);  // 32 KB
        k_gather<16><<<grid, 256, smem>>>(x2, D_IP1, SA, NA, iwA, ip1);
    }

    // 8) final interpolation rows [128, 896)
    {
        cudaFuncSetAttribute(k_final<8>, cudaFuncAttributeMaxDynamicSharedMemorySize,
                             8 * 2048 * (int)sizeof(float));
        dim3 grid((DOUT - 128) / 8, BATCH);
        size_t smem = 8 * 2048 * sizeof(float);  // 64 KB
        k_final<8><<<grid, 512, smem>>>(x1, ip1, iwB, out);
    }
}